// round 1
// baseline (speedup 1.0000x reference)
#include <cuda_runtime.h>

#define N_POINTS_EXPECTED 2097152

// Cell record: 5 float4s per cell
//  v0: ax, ay, bx, by
//  v1: cx, cy, d0x(=bx-ax), d0y(=by-ay)
//  v2: d1x(=cx-bx), d1y(=cy-by), d2x(=ax-cx), d2y(=ay-cy)
//  v3: ocx, ocy, r2, ecx
//  v4: ecy, 1/erx, 1/ery, pad
__global__ __launch_bounds__(256)
void vg_kernel(const float* __restrict__ x, const float* __restrict__ p,
               float* __restrict__ out, int n)
{
    __shared__ float4 rec[25 * 5];
    __shared__ float colors[76 * 3];   // slot 0 = black (best == -1)

    const int tid = threadIdx.x;

    if (tid < 25) {
        const float* q = p + tid * 28;
        float ax = q[1], ay = q[2], bx = q[3], by = q[4], cx = q[5], cy = q[6];
        rec[tid * 5 + 0] = make_float4(ax, ay, bx, by);
        rec[tid * 5 + 1] = make_float4(cx, cy, __fsub_rn(bx, ax), __fsub_rn(by, ay));
        rec[tid * 5 + 2] = make_float4(__fsub_rn(cx, bx), __fsub_rn(cy, by),
                                       __fsub_rn(ax, cx), __fsub_rn(ay, cy));
        float ocx = q[12], ocy = q[13], r = q[14];
        float ecx = q[20], ecy = q[21], erx = q[22], ery = q[23];
        rec[tid * 5 + 3] = make_float4(ocx, ocy, __fmul_rn(r, r), ecx);
        rec[tid * 5 + 4] = make_float4(ecy, 1.0f / erx, 1.0f / ery, 0.0f);
    }
    // color table: shape id s (0..74) at colors[3 + 3*s + k]
    for (int idx = tid; idx < 228; idx += 256) {
        if (idx < 3) {
            colors[idx] = 0.0f;
        } else {
            int s = (idx - 3) / 3, k = (idx - 3) % 3;
            int c = s / 3, t = s % 3;
            int off = (t == 0) ? (8 + k) : ((t == 1) ? (16 + k) : (25 + k));
            colors[idx] = p[c * 28 + off];
        }
    }
    __syncthreads();

    int gid = blockIdx.x * blockDim.x + tid;
    if (gid >= n) return;

    float2 pt = ((const float2*)x)[gid];
    const float px = pt.x, py = pt.y;

    int ci = (int)(px * 5.0f); ci = ci > 4 ? 4 : (ci < 0 ? 0 : ci);
    int cj = (int)(py * 5.0f); cj = cj > 4 ? 4 : (cj < 0 ? 0 : cj);

    int best = -1;

#pragma unroll
    for (int di = -1; di <= 1; di++) {
#pragma unroll
        for (int dj = -1; dj <= 1; dj++) {
            int i = ci + di, j = cj + dj;
            bool valid = ((unsigned)i <= 4u) && ((unsigned)j <= 4u);
            int ii = i < 0 ? 0 : (i > 4 ? 4 : i);
            int jj = j < 0 ? 0 : (j > 4 ? 4 : j);
            int c = ii * 5 + jj;

            float4 v0 = rec[c * 5 + 0];
            float4 v1 = rec[c * 5 + 1];
            float4 v2 = rec[c * 5 + 2];
            float4 v3 = rec[c * 5 + 3];
            float4 v4 = rec[c * 5 + 4];

            // Triangle: exact same op order as reference (no fma contraction)
            float e0 = __fsub_rn(__fmul_rn(__fsub_rn(px, v0.x), v1.w),
                                 __fmul_rn(__fsub_rn(py, v0.y), v1.z));
            float e1 = __fsub_rn(__fmul_rn(__fsub_rn(px, v0.z), v2.y),
                                 __fmul_rn(__fsub_rn(py, v0.w), v2.x));
            float e2 = __fsub_rn(__fmul_rn(__fsub_rn(px, v1.x), v2.w),
                                 __fmul_rn(__fsub_rn(py, v1.y), v2.z));
            float emin = fminf(fminf(e0, e1), e2);
            float emax = fmaxf(fmaxf(e0, e1), e2);
            bool tri_in = (emin >= 0.0f) || (emax <= 0.0f);

            // Circle
            float dx = __fsub_rn(px, v3.x), dy = __fsub_rn(py, v3.y);
            bool circ_in = __fadd_rn(__fmul_rn(dx, dx), __fmul_rn(dy, dy)) <= v3.z;

            // Ellipse (1/r precomputed; steep gradient makes rounding band negligible)
            float xn = __fmul_rn(__fsub_rn(px, v3.w), v4.y);
            float yn = __fmul_rn(__fsub_rn(py, v4.x), v4.z);
            bool ell_in = __fadd_rn(__fmul_rn(xn, xn), __fmul_rn(yn, yn)) <= 1.0f;

            int c3 = c * 3;
            int cb = tri_in ? c3 : -1;
            cb = circ_in ? c3 + 1 : cb;
            cb = ell_in ? c3 + 2 : cb;
            cb = valid ? cb : -1;
            best = best > cb ? best : cb;
        }
    }

    int cbase = (best + 1) * 3;
    out[gid * 3 + 0] = colors[cbase + 0];
    out[gid * 3 + 1] = colors[cbase + 1];
    out[gid * 3 + 2] = colors[cbase + 2];
}

extern "C" void kernel_launch(void* const* d_in, const int* in_sizes, int n_in,
                              void* d_out, int out_size)
{
    // Identify inputs robustly: x has 2*N elements, p has 700
    int xi = 0, pi = 1;
    if (n_in >= 2 && in_sizes[0] < in_sizes[1]) { xi = 1; pi = 0; }
    const float* x = (const float*)d_in[xi];
    const float* p = (const float*)d_in[pi];
    float* out = (float*)d_out;

    int n = in_sizes[xi] / 2;
    int blocks = (n + 255) / 256;
    vg_kernel<<<blocks, 256>>>(x, p, out, n);
}

// round 2
// speedup vs baseline: 1.0029x; 1.0029x over previous
#include <cuda_runtime.h>

#define N_POINTS_EXPECTED 2097152

// Cell record: 5 float4s per cell
//  v0: ax, ay, bx, by
//  v1: cx, cy, d0x(=bx-ax), d0y(=by-ay)
//  v2: d1x(=cx-bx), d1y(=cy-by), d2x(=ax-cx), d2y(=ay-cy)
//  v3: ocx, ocy, r2, ecx
//  v4: ecy, 1/erx, 1/ery, pad
__global__ __launch_bounds__(256)
void vg_kernel(const float* __restrict__ x, const float* __restrict__ p,
               float* __restrict__ out, int n)
{
    __shared__ float4 rec[25 * 5];
    __shared__ float colors[76 * 3];   // slot 0 = black (best == -1)

    const int tid = threadIdx.x;

    if (tid < 25) {
        const float* q = p + tid * 28;
        float ax = q[1], ay = q[2], bx = q[3], by = q[4], cx = q[5], cy = q[6];
        rec[tid * 5 + 0] = make_float4(ax, ay, bx, by);
        rec[tid * 5 + 1] = make_float4(cx, cy, __fsub_rn(bx, ax), __fsub_rn(by, ay));
        rec[tid * 5 + 2] = make_float4(__fsub_rn(cx, bx), __fsub_rn(cy, by),
                                       __fsub_rn(ax, cx), __fsub_rn(ay, cy));
        float ocx = q[12], ocy = q[13], r = q[14];
        float ecx = q[20], ecy = q[21], erx = q[22], ery = q[23];
        rec[tid * 5 + 3] = make_float4(ocx, ocy, __fmul_rn(r, r), ecx);
        rec[tid * 5 + 4] = make_float4(ecy, 1.0f / erx, 1.0f / ery, 0.0f);
    }
    // color table: shape id s (0..74) at colors[3 + 3*s + k]
    for (int idx = tid; idx < 228; idx += 256) {
        if (idx < 3) {
            colors[idx] = 0.0f;
        } else {
            int s = (idx - 3) / 3, k = (idx - 3) % 3;
            int c = s / 3, t = s % 3;
            int off = (t == 0) ? (8 + k) : ((t == 1) ? (16 + k) : (25 + k));
            colors[idx] = p[c * 28 + off];
        }
    }
    __syncthreads();

    int gid = blockIdx.x * blockDim.x + tid;
    if (gid >= n) return;

    float2 pt = ((const float2*)x)[gid];
    const float px = pt.x, py = pt.y;

    int ci = (int)(px * 5.0f); ci = ci > 4 ? 4 : (ci < 0 ? 0 : ci);
    int cj = (int)(py * 5.0f); cj = cj > 4 ? 4 : (cj < 0 ? 0 : cj);

    int best = -1;

#pragma unroll
    for (int di = -1; di <= 1; di++) {
#pragma unroll
        for (int dj = -1; dj <= 1; dj++) {
            int i = ci + di, j = cj + dj;
            bool valid = ((unsigned)i <= 4u) && ((unsigned)j <= 4u);
            int ii = i < 0 ? 0 : (i > 4 ? 4 : i);
            int jj = j < 0 ? 0 : (j > 4 ? 4 : j);
            int c = ii * 5 + jj;

            float4 v0 = rec[c * 5 + 0];
            float4 v1 = rec[c * 5 + 1];
            float4 v2 = rec[c * 5 + 2];
            float4 v3 = rec[c * 5 + 3];
            float4 v4 = rec[c * 5 + 4];

            // Triangle: exact same op order as reference (no fma contraction)
            float e0 = __fsub_rn(__fmul_rn(__fsub_rn(px, v0.x), v1.w),
                                 __fmul_rn(__fsub_rn(py, v0.y), v1.z));
            float e1 = __fsub_rn(__fmul_rn(__fsub_rn(px, v0.z), v2.y),
                                 __fmul_rn(__fsub_rn(py, v0.w), v2.x));
            float e2 = __fsub_rn(__fmul_rn(__fsub_rn(px, v1.x), v2.w),
                                 __fmul_rn(__fsub_rn(py, v1.y), v2.z));
            float emin = fminf(fminf(e0, e1), e2);
            float emax = fmaxf(fmaxf(e0, e1), e2);
            bool tri_in = (emin >= 0.0f) || (emax <= 0.0f);

            // Circle
            float dx = __fsub_rn(px, v3.x), dy = __fsub_rn(py, v3.y);
            bool circ_in = __fadd_rn(__fmul_rn(dx, dx), __fmul_rn(dy, dy)) <= v3.z;

            // Ellipse (1/r precomputed; steep gradient makes rounding band negligible)
            float xn = __fmul_rn(__fsub_rn(px, v3.w), v4.y);
            float yn = __fmul_rn(__fsub_rn(py, v4.x), v4.z);
            bool ell_in = __fadd_rn(__fmul_rn(xn, xn), __fmul_rn(yn, yn)) <= 1.0f;

            int c3 = c * 3;
            int cb = tri_in ? c3 : -1;
            cb = circ_in ? c3 + 1 : cb;
            cb = ell_in ? c3 + 2 : cb;
            cb = valid ? cb : -1;
            best = best > cb ? best : cb;
        }
    }

    int cbase = (best + 1) * 3;
    out[gid * 3 + 0] = colors[cbase + 0];
    out[gid * 3 + 1] = colors[cbase + 1];
    out[gid * 3 + 2] = colors[cbase + 2];
}

extern "C" void kernel_launch(void* const* d_in, const int* in_sizes, int n_in,
                              void* d_out, int out_size)
{
    // Identify inputs robustly: x has 2*N elements, p has 700
    int xi = 0, pi = 1;
    if (n_in >= 2 && in_sizes[0] < in_sizes[1]) { xi = 1; pi = 0; }
    const float* x = (const float*)d_in[xi];
    const float* p = (const float*)d_in[pi];
    float* out = (float*)d_out;

    int n = in_sizes[xi] / 2;
    int blocks = (n + 255) / 256;
    vg_kernel<<<blocks, 256>>>(x, p, out, n);
}

// round 3
// speedup vs baseline: 1.6325x; 1.6277x over previous
#include <cuda_runtime.h>

// Cell record: 5 float4s per cell
//  v0: ax, ay, bx, by
//  v1: cx, cy, d0x(=bx-ax), d0y(=by-ay)
//  v2: d1x(=cx-bx), d1y(=cy-by), d2x(=ax-cx), d2y(=ay-cy)
//  v3: ocx, ocy, r2, ecx
//  v4: ecy, 1/erx, 1/ery, pad
__global__ __launch_bounds__(256)
void vg_kernel(const float* __restrict__ x, const float* __restrict__ p,
               float* __restrict__ out, int n)
{
    __shared__ float4 rec[25 * 5];
    __shared__ float colors[76 * 3];        // slot 0 = black (best == -1)
    __shared__ float spx[256], spy[256];    // cell-sorted points
    __shared__ unsigned short smeta[256];   // orig lane | cell<<8
    __shared__ int hist[25];
    __shared__ int off[25];
    __shared__ float scol[768];             // RGB planes in original order

    const int tid = threadIdx.x;

    if (tid < 25) {
        const float* q = p + tid * 28;
        float ax = q[1], ay = q[2], bx = q[3], by = q[4], cx = q[5], cy = q[6];
        rec[tid * 5 + 0] = make_float4(ax, ay, bx, by);
        rec[tid * 5 + 1] = make_float4(cx, cy, __fsub_rn(bx, ax), __fsub_rn(by, ay));
        rec[tid * 5 + 2] = make_float4(__fsub_rn(cx, bx), __fsub_rn(cy, by),
                                       __fsub_rn(ax, cx), __fsub_rn(ay, cy));
        float ocx = q[12], ocy = q[13], r = q[14];
        float ecx = q[20], ecy = q[21], erx = q[22], ery = q[23];
        rec[tid * 5 + 3] = make_float4(ocx, ocy, __fmul_rn(r, r), ecx);
        rec[tid * 5 + 4] = make_float4(ecy, 1.0f / erx, 1.0f / ery, 0.0f);
        hist[tid] = 0;
    }
    // color table: shape id s (0..74) at colors[3 + 3*s + k]
    for (int idx = tid; idx < 228; idx += 256) {
        if (idx < 3) {
            colors[idx] = 0.0f;
        } else {
            int s = (idx - 3) / 3, k = (idx - 3) % 3;
            int c = s / 3, t = s % 3;
            int o = (t == 0) ? (8 + k) : ((t == 1) ? (16 + k) : (25 + k));
            colors[idx] = p[c * 28 + o];
        }
    }
    __syncthreads();

    // ---- Phase 1: load point, compute cell, histogram ----
    int gid = blockIdx.x * 256 + tid;
    bool live = gid < n;
    float2 pt = live ? ((const float2*)x)[gid] : make_float2(0.5f, 0.5f);
    int ci = (int)(pt.x * 5.0f); ci = ci > 4 ? 4 : (ci < 0 ? 0 : ci);
    int cj = (int)(pt.y * 5.0f); cj = cj > 4 ? 4 : (cj < 0 ? 0 : cj);
    int c = ci * 5 + cj;
    int rank = atomicAdd(&hist[c], 1);
    __syncthreads();

    // ---- Phase 2: exclusive scan of 25 bins (warp 0) ----
    if (tid < 32) {
        int v = (tid < 25) ? hist[tid] : 0;
        int s = v;
#pragma unroll
        for (int d = 1; d < 32; d <<= 1) {
            int t = __shfl_up_sync(0xffffffff, s, d);
            if (tid >= d) s += t;
        }
        if (tid < 25) off[tid] = s - v;
    }
    __syncthreads();

    // ---- Phase 3: scatter into cell-sorted order ----
    int pos = off[c] + rank;
    spx[pos] = pt.x;
    spy[pos] = pt.y;
    smeta[pos] = (unsigned short)(tid | (c << 8));
    __syncthreads();

    // ---- Phase 4: per-point work on sorted slot (warp-coherent cells) ----
    const float px = spx[tid];
    const float py = spy[tid];
    unsigned int meta = smeta[tid];
    int mc = meta >> 8;
    ci = mc / 5;
    cj = mc - ci * 5;

    int best = -1;

#pragma unroll
    for (int di = -1; di <= 1; di++) {
#pragma unroll
        for (int dj = -1; dj <= 1; dj++) {
            int i = ci + di, j = cj + dj;
            bool valid = ((unsigned)i <= 4u) && ((unsigned)j <= 4u);
            int ii = i < 0 ? 0 : (i > 4 ? 4 : i);
            int jj = j < 0 ? 0 : (j > 4 ? 4 : j);
            int cc = ii * 5 + jj;

            float4 v0 = rec[cc * 5 + 0];
            float4 v1 = rec[cc * 5 + 1];
            float4 v2 = rec[cc * 5 + 2];
            float4 v3 = rec[cc * 5 + 3];
            float4 v4 = rec[cc * 5 + 4];

            // Triangle: exact same op order as reference (no fma contraction)
            float e0 = __fsub_rn(__fmul_rn(__fsub_rn(px, v0.x), v1.w),
                                 __fmul_rn(__fsub_rn(py, v0.y), v1.z));
            float e1 = __fsub_rn(__fmul_rn(__fsub_rn(px, v0.z), v2.y),
                                 __fmul_rn(__fsub_rn(py, v0.w), v2.x));
            float e2 = __fsub_rn(__fmul_rn(__fsub_rn(px, v1.x), v2.w),
                                 __fmul_rn(__fsub_rn(py, v1.y), v2.z));
            float emin = fminf(fminf(e0, e1), e2);
            float emax = fmaxf(fmaxf(e0, e1), e2);
            bool tri_in = (emin >= 0.0f) || (emax <= 0.0f);

            // Circle
            float dx = __fsub_rn(px, v3.x), dy = __fsub_rn(py, v3.y);
            bool circ_in = __fadd_rn(__fmul_rn(dx, dx), __fmul_rn(dy, dy)) <= v3.z;

            // Ellipse
            float xn = __fmul_rn(__fsub_rn(px, v3.w), v4.y);
            float yn = __fmul_rn(__fsub_rn(py, v4.x), v4.z);
            bool ell_in = __fadd_rn(__fmul_rn(xn, xn), __fmul_rn(yn, yn)) <= 1.0f;

            int c3 = cc * 3;
            int cb = tri_in ? c3 : -1;
            cb = circ_in ? c3 + 1 : cb;
            cb = ell_in ? c3 + 2 : cb;
            cb = valid ? cb : -1;
            best = best > cb ? best : cb;
        }
    }

    // ---- Phase 5: write color to shared in ORIGINAL lane order ----
    int orig = meta & 0xff;
    int cbase = (best + 1) * 3;
    scol[orig * 3 + 0] = colors[cbase + 0];
    scol[orig * 3 + 1] = colors[cbase + 1];
    scol[orig * 3 + 2] = colors[cbase + 2];
    __syncthreads();

    // ---- Phase 6: fully coalesced store ----
    int base = blockIdx.x * 768;
    int total = n * 3;
#pragma unroll
    for (int k = 0; k < 3; k++) {
        int o = base + k * 256 + tid;
        if (o < total) out[o] = scol[k * 256 + tid];
    }
}

extern "C" void kernel_launch(void* const* d_in, const int* in_sizes, int n_in,
                              void* d_out, int out_size)
{
    // Identify inputs robustly: x has 2*N elements, p has 700
    int xi = 0, pi = 1;
    if (n_in >= 2 && in_sizes[0] < in_sizes[1]) { xi = 1; pi = 0; }
    const float* x = (const float*)d_in[xi];
    const float* p = (const float*)d_in[pi];
    float* out = (float*)d_out;

    int n = in_sizes[xi] / 2;
    int blocks = (n + 255) / 256;
    vg_kernel<<<blocks, 256>>>(x, p, out, n);
}

// round 4
// speedup vs baseline: 2.3579x; 1.4443x over previous
#include <cuda_runtime.h>

// Cell record: 5 float4s per cell
//  v0: ax, ay, bx, by
//  v1: cx, cy, d0x(=bx-ax), d0y(=by-ay)
//  v2: d1x(=cx-bx), d1y(=cy-by), d2x(=ax-cx), d2y(=ay-cy)
//  v3: ocx, ocy, r2, ecx
//  v4: ecy, 1/erx, 1/ery, pad
__global__ __launch_bounds__(256)
void vg_kernel(const float* __restrict__ x, const float* __restrict__ p,
               float* __restrict__ out, int n)
{
    __shared__ float4 rec[25 * 5];
    __shared__ float colors[76 * 3];        // slot 0 = black (best == -1)
    __shared__ float spx[256], spy[256];    // cell-sorted points
    __shared__ unsigned short smeta[256];   // orig lane | cell<<8
    __shared__ int hist[25];
    __shared__ int off[25];
    __shared__ float scol[768];             // RGB in original order

    const int tid = threadIdx.x;

    if (tid < 25) {
        const float* q = p + tid * 28;
        float ax = q[1], ay = q[2], bx = q[3], by = q[4], cx = q[5], cy = q[6];
        rec[tid * 5 + 0] = make_float4(ax, ay, bx, by);
        rec[tid * 5 + 1] = make_float4(cx, cy, __fsub_rn(bx, ax), __fsub_rn(by, ay));
        rec[tid * 5 + 2] = make_float4(__fsub_rn(cx, bx), __fsub_rn(cy, by),
                                       __fsub_rn(ax, cx), __fsub_rn(ay, cy));
        float ocx = q[12], ocy = q[13], r = q[14];
        float ecx = q[20], ecy = q[21], erx = q[22], ery = q[23];
        rec[tid * 5 + 3] = make_float4(ocx, ocy, __fmul_rn(r, r), ecx);
        rec[tid * 5 + 4] = make_float4(ecy, 1.0f / erx, 1.0f / ery, 0.0f);
        hist[tid] = 0;
    }
    // color table: shape id s (0..74) at colors[3 + 3*s + k]
    for (int idx = tid; idx < 228; idx += 256) {
        if (idx < 3) {
            colors[idx] = 0.0f;
        } else {
            int s = (idx - 3) / 3, k = (idx - 3) % 3;
            int c = s / 3, t = s % 3;
            int o = (t == 0) ? (8 + k) : ((t == 1) ? (16 + k) : (25 + k));
            colors[idx] = p[c * 28 + o];
        }
    }
    __syncthreads();

    // ---- Phase 1: load point, compute cell, histogram ----
    int gid = blockIdx.x * 256 + tid;
    bool live = gid < n;
    float2 pt = live ? ((const float2*)x)[gid] : make_float2(0.5f, 0.5f);
    int ci = (int)(pt.x * 5.0f); ci = ci > 4 ? 4 : (ci < 0 ? 0 : ci);
    int cj = (int)(pt.y * 5.0f); cj = cj > 4 ? 4 : (cj < 0 ? 0 : cj);
    int c = ci * 5 + cj;
    int rank = atomicAdd(&hist[c], 1);
    __syncthreads();

    // ---- Phase 2: exclusive scan of 25 bins (warp 0) ----
    if (tid < 32) {
        int v = (tid < 25) ? hist[tid] : 0;
        int s = v;
#pragma unroll
        for (int d = 1; d < 32; d <<= 1) {
            int t = __shfl_up_sync(0xffffffff, s, d);
            if (tid >= d) s += t;
        }
        if (tid < 25) off[tid] = s - v;
    }
    __syncthreads();

    // ---- Phase 3: scatter into cell-sorted order ----
    int pos = off[c] + rank;
    spx[pos] = pt.x;
    spy[pos] = pt.y;
    smeta[pos] = (unsigned short)(tid | (c << 8));
    __syncthreads();

    // ---- Phase 4: per-point work on sorted slot ----
    const float px = spx[tid];
    const float py = spy[tid];
    unsigned int meta = smeta[tid];
    int mc = meta >> 8;
    ci = mc / 5;
    cj = mc - ci * 5;

    // Candidate neighbor per axis: shapes extend at most 0.4 cell-widths
    // outside their cell, so the left neighbor matters only for f<=0.41,
    // the right only for f>=0.59 (0.01cw safety margin >> fp rounding).
    float fx = px * 5.0f - (float)ci;
    float fy = py * 5.0f - (float)cj;
    int ci2 = (fx <= 0.41f) ? ci - 1 : ((fx >= 0.59f) ? ci + 1 : ci);
    int cj2 = (fy <= 0.41f) ? cj - 1 : ((fy >= 0.59f) ? cj + 1 : cj);
    bool vx = (ci2 != ci) && ((unsigned)ci2 <= 4u);
    bool vy = (cj2 != cj) && ((unsigned)cj2 <= 4u);
    int ci2c = ci2 < 0 ? 0 : (ci2 > 4 ? 4 : ci2);
    int cj2c = cj2 < 0 ? 0 : (cj2 > 4 ? 4 : cj2);

    int ia[2] = { ci, ci2c };
    int ja[2] = { cj, cj2c };
    bool va[2] = { true, vx };
    bool vb[2] = { true, vy };

    int best = -1;

#pragma unroll
    for (int a = 0; a < 2; a++) {
#pragma unroll
        for (int b = 0; b < 2; b++) {
            bool valid = va[a] && vb[b];
            int cc = ia[a] * 5 + ja[b];

            float4 v0 = rec[cc * 5 + 0];
            float4 v1 = rec[cc * 5 + 1];
            float4 v2 = rec[cc * 5 + 2];
            float4 v3 = rec[cc * 5 + 3];
            float4 v4 = rec[cc * 5 + 4];

            // Triangle: exact same op order as reference (no fma contraction)
            float e0 = __fsub_rn(__fmul_rn(__fsub_rn(px, v0.x), v1.w),
                                 __fmul_rn(__fsub_rn(py, v0.y), v1.z));
            float e1 = __fsub_rn(__fmul_rn(__fsub_rn(px, v0.z), v2.y),
                                 __fmul_rn(__fsub_rn(py, v0.w), v2.x));
            float e2 = __fsub_rn(__fmul_rn(__fsub_rn(px, v1.x), v2.w),
                                 __fmul_rn(__fsub_rn(py, v1.y), v2.z));
            float emin = fminf(fminf(e0, e1), e2);
            float emax = fmaxf(fmaxf(e0, e1), e2);
            bool tri_in = (emin >= 0.0f) || (emax <= 0.0f);

            // Circle
            float dx = __fsub_rn(px, v3.x), dy = __fsub_rn(py, v3.y);
            bool circ_in = __fadd_rn(__fmul_rn(dx, dx), __fmul_rn(dy, dy)) <= v3.z;

            // Ellipse
            float xn = __fmul_rn(__fsub_rn(px, v3.w), v4.y);
            float yn = __fmul_rn(__fsub_rn(py, v4.x), v4.z);
            bool ell_in = __fadd_rn(__fmul_rn(xn, xn), __fmul_rn(yn, yn)) <= 1.0f;

            int c3 = cc * 3;
            int cb = tri_in ? c3 : -1;
            cb = circ_in ? c3 + 1 : cb;
            cb = ell_in ? c3 + 2 : cb;
            cb = valid ? cb : -1;
            best = best > cb ? best : cb;
        }
    }

    // ---- Phase 5: write color to shared in ORIGINAL lane order ----
    int orig = meta & 0xff;
    int cbase = (best + 1) * 3;
    scol[orig * 3 + 0] = colors[cbase + 0];
    scol[orig * 3 + 1] = colors[cbase + 1];
    scol[orig * 3 + 2] = colors[cbase + 2];
    __syncthreads();

    // ---- Phase 6: fully coalesced store ----
    int base = blockIdx.x * 768;
    int total = n * 3;
#pragma unroll
    for (int k = 0; k < 3; k++) {
        int o = base + k * 256 + tid;
        if (o < total) out[o] = scol[k * 256 + tid];
    }
}

extern "C" void kernel_launch(void* const* d_in, const int* in_sizes, int n_in,
                              void* d_out, int out_size)
{
    // Identify inputs robustly: x has 2*N elements, p has 700
    int xi = 0, pi = 1;
    if (n_in >= 2 && in_sizes[0] < in_sizes[1]) { xi = 1; pi = 0; }
    const float* x = (const float*)d_in[xi];
    const float* p = (const float*)d_in[pi];
    float* out = (float*)d_out;

    int n = in_sizes[xi] / 2;
    int blocks = (n + 255) / 256;
    vg_kernel<<<blocks, 256>>>(x, p, out, n);
}

// round 5
// speedup vs baseline: 3.0231x; 1.2821x over previous
#include <cuda_runtime.h>

#define TPB  256
#define PPT  4
#define TILE (TPB * PPT)   // 1024 points per block

// Cell record (13 floats, packed as 3 x float4 + 1 scalar):
//  r0: ax, ay, bx, by
//  r1: cx, cy, ocx, ocy
//  r2: r*r, ecx, ecy, 1/erx
//  siery: 1/ery
__global__ __launch_bounds__(TPB)
void vg_kernel(const float* __restrict__ x, const float* __restrict__ p,
               float* __restrict__ out, int n)
{
    __shared__ float4 rec4[25 * 3];
    __shared__ float  siery[25];
    __shared__ float  colors[76 * 3];      // slot 0 = black
    __shared__ float2 sp[TILE];            // cell+quadrant-sorted points
    __shared__ unsigned short sorig[TILE]; // original local index
    __shared__ unsigned int   stmp[TILE];  // key | rank<<8
    __shared__ unsigned char  sbest[TILE]; // winner (+1) per original point
    __shared__ int hist[225];
    __shared__ int off[225];
    __shared__ int wsum[8];

    const int tid = threadIdx.x;

    if (tid < 25) {
        const float* q = p + tid * 28;
        float ax = q[1],  ay = q[2],  bx = q[3],  by = q[4], cx = q[5], cy = q[6];
        float ocx = q[12], ocy = q[13], r = q[14];
        float ecx = q[20], ecy = q[21], erx = q[22], ery = q[23];
        rec4[tid * 3 + 0] = make_float4(ax, ay, bx, by);
        rec4[tid * 3 + 1] = make_float4(cx, cy, ocx, ocy);
        rec4[tid * 3 + 2] = make_float4(__fmul_rn(r, r), ecx, ecy, 1.0f / erx);
        siery[tid] = 1.0f / ery;
    }
    for (int idx = tid; idx < 228; idx += TPB) {
        if (idx < 3) colors[idx] = 0.0f;
        else {
            int s = (idx - 3) / 3, k = (idx - 3) % 3;
            int c = s / 3, t = s % 3;
            int o = (t == 0) ? (8 + k) : ((t == 1) ? (16 + k) : (25 + k));
            colors[idx] = p[c * 28 + o];
        }
    }
    if (tid < 225) hist[tid] = 0;
    __syncthreads();

    const int base = blockIdx.x * TILE;

    // ---- Phase 1: load points, compute sort key, histogram ----
    float2 pts[PPT];
#pragma unroll
    for (int k = 0; k < PPT; k++) {
        int li = k * TPB + tid;
        int gi = base + li;
        float2 pt = (gi < n) ? ((const float2*)x)[gi] : make_float2(0.5f, 0.5f);
        pts[k] = pt;
        int ci = (int)(pt.x * 5.0f); ci = ci > 4 ? 4 : (ci < 0 ? 0 : ci);
        int cj = (int)(pt.y * 5.0f); cj = cj > 4 ? 4 : (cj < 0 ? 0 : cj);
        float fx = pt.x * 5.0f - (float)ci;
        float fy = pt.y * 5.0f - (float)cj;
        int qx = (fx <= 0.41f) ? 0 : ((fx >= 0.59f) ? 2 : 1);
        int qy = (fy <= 0.41f) ? 0 : ((fy >= 0.59f) ? 2 : 1);
        int key = (ci * 5 + cj) * 9 + qx * 3 + qy;
        int rank = atomicAdd(&hist[key], 1);
        stmp[li] = (unsigned)key | ((unsigned)rank << 8);
    }
    __syncthreads();

    // ---- Phase 2: exclusive scan of 225 bins (two-level shuffle scan) ----
    {
        int v = (tid < 225) ? hist[tid] : 0;
        int s = v;
#pragma unroll
        for (int d = 1; d < 32; d <<= 1) {
            int t = __shfl_up_sync(0xffffffff, s, d);
            if ((tid & 31) >= d) s += t;
        }
        if ((tid & 31) == 31) wsum[tid >> 5] = s;
        __syncthreads();
        if (tid < 8) {
            int w = wsum[tid];
            int sw = w;
#pragma unroll
            for (int d = 1; d < 8; d <<= 1) {
                int t = __shfl_up_sync(0xff, sw, d);
                if (tid >= d) sw += t;
            }
            wsum[tid] = sw - w;    // exclusive warp base
        }
        // reset hist for next launch reuse not needed (non-persistent)
        __syncthreads();
        if (tid < 225) off[tid] = (s - v) + wsum[tid >> 5];
    }
    __syncthreads();

    // ---- Phase 3: scatter into (cell,quadrant)-sorted order ----
#pragma unroll
    for (int k = 0; k < PPT; k++) {
        int li = k * TPB + tid;
        unsigned t = stmp[li];
        int key = t & 0xff;
        int rank = (int)(t >> 8);
        int pos = off[key] + rank;
        sp[pos] = pts[k];
        sorig[pos] = (unsigned short)li;
    }
    __syncthreads();

    // ---- Phase 4: shade sorted points (warp-uniform candidate cells) ----
#pragma unroll 1
    for (int k = 0; k < PPT; k++) {
        int li = k * TPB + tid;
        float2 pt = sp[li];
        const float px = pt.x, py = pt.y;
        int ci = (int)(px * 5.0f); ci = ci > 4 ? 4 : (ci < 0 ? 0 : ci);
        int cj = (int)(py * 5.0f); cj = cj > 4 ? 4 : (cj < 0 ? 0 : cj);
        float fx = px * 5.0f - (float)ci;
        float fy = py * 5.0f - (float)cj;
        // shapes extend at most 0.4 cell-widths outside their cell;
        // 0.41/0.59 thresholds leave a 0.002-abs margin >> f32 rounding
        int dxn = (fx <= 0.41f) ? -1 : ((fx >= 0.59f) ? 1 : 0);
        int dyn = (fy <= 0.41f) ? -1 : ((fy >= 0.59f) ? 1 : 0);
        int i2 = ci + dxn, j2 = cj + dyn;
        bool vx = (dxn != 0) && ((unsigned)i2 <= 4u);
        bool vy = (dyn != 0) && ((unsigned)j2 <= 4u);
        int i2c = i2 < 0 ? 0 : (i2 > 4 ? 4 : i2);
        int j2c = j2 < 0 ? 0 : (j2 > 4 ? 4 : j2);

        int  ia[2] = { ci, i2c };
        int  ja[2] = { cj, j2c };
        bool va[2] = { true, vx };
        bool vb[2] = { true, vy };

        int best = -1;
#pragma unroll
        for (int a = 0; a < 2; a++) {
#pragma unroll
            for (int b = 0; b < 2; b++) {
                bool valid = va[a] && vb[b];
                int cc = ia[a] * 5 + ja[b];

                float4 r0  = rec4[cc * 3 + 0];
                float4 r1  = rec4[cc * 3 + 1];
                float4 r2v = rec4[cc * 3 + 2];
                float  iery = siery[cc];

                // edge deltas recomputed in registers (bit-identical fsub)
                float d0x = __fsub_rn(r0.z, r0.x), d0y = __fsub_rn(r0.w, r0.y);
                float d1x = __fsub_rn(r1.x, r0.z), d1y = __fsub_rn(r1.y, r0.w);
                float d2x = __fsub_rn(r0.x, r1.x), d2y = __fsub_rn(r0.y, r1.y);

                // Triangle: exact reference op order (no fma contraction)
                float e0 = __fsub_rn(__fmul_rn(__fsub_rn(px, r0.x), d0y),
                                     __fmul_rn(__fsub_rn(py, r0.y), d0x));
                float e1 = __fsub_rn(__fmul_rn(__fsub_rn(px, r0.z), d1y),
                                     __fmul_rn(__fsub_rn(py, r0.w), d1x));
                float e2 = __fsub_rn(__fmul_rn(__fsub_rn(px, r1.x), d2y),
                                     __fmul_rn(__fsub_rn(py, r1.y), d2x));
                float emin = fminf(fminf(e0, e1), e2);
                float emax = fmaxf(fmaxf(e0, e1), e2);
                bool tri_in = (emin >= 0.0f) || (emax <= 0.0f);

                // Circle
                float dx = __fsub_rn(px, r1.z), dy = __fsub_rn(py, r1.w);
                bool circ_in = __fadd_rn(__fmul_rn(dx, dx), __fmul_rn(dy, dy)) <= r2v.x;

                // Ellipse
                float xn = __fmul_rn(__fsub_rn(px, r2v.y), r2v.w);
                float yn = __fmul_rn(__fsub_rn(py, r2v.z), iery);
                bool ell_in = __fadd_rn(__fmul_rn(xn, xn), __fmul_rn(yn, yn)) <= 1.0f;

                int c3 = cc * 3;
                int cb = tri_in  ? c3     : -1;
                cb     = circ_in ? c3 + 1 : cb;
                cb     = ell_in  ? c3 + 2 : cb;
                cb     = valid   ? cb     : -1;
                best = best > cb ? best : cb;
            }
        }
        sbest[sorig[li]] = (unsigned char)(best + 1);
    }
    __syncthreads();

    // ---- Phase 5: output in original order (dense 384B/warp stores) ----
#pragma unroll
    for (int k = 0; k < PPT; k++) {
        int li = k * TPB + tid;
        int gi = base + li;
        if (gi < n) {
            int cb = (int)sbest[li] * 3;
            out[gi * 3 + 0] = colors[cb + 0];
            out[gi * 3 + 1] = colors[cb + 1];
            out[gi * 3 + 2] = colors[cb + 2];
        }
    }
}

extern "C" void kernel_launch(void* const* d_in, const int* in_sizes, int n_in,
                              void* d_out, int out_size)
{
    // Identify inputs robustly: x has 2*N elements, p has 700
    int xi = 0, pi = 1;
    if (n_in >= 2 && in_sizes[0] < in_sizes[1]) { xi = 1; pi = 0; }
    const float* x = (const float*)d_in[xi];
    const float* p = (const float*)d_in[pi];
    float* out = (float*)d_out;

    int n = in_sizes[xi] / 2;
    int blocks = (n + TILE - 1) / TILE;
    vg_kernel<<<blocks, TPB>>>(x, p, out, n);
}